// round 3
// baseline (speedup 1.0000x reference)
#include <cuda_runtime.h>
#include <cuda_bf16.h>
#include <math.h>

// ---------------- problem constants ----------------
#define S_   1024
#define H_   32
#define KVH_ 8
#define DH_  128
#define D_   4096
#define CB_  16
#define NC_  64        // S/CB
#define SB_  16
#define NSEL_ 4
#define WIN_ 64
#define NQKV_ 6144     // H*DH + 2*KVH*DH
#define CDIM_ 2048     // CB*DH
#define NEGF (-3.402823466e38f)
#define SCALE_ 0.08838834764831844056f  // 128^-0.5

// ---------------- scratch (no allocs allowed) ----------------
__device__ float g_qkv [S_ * NQKV_];          // [s][6144]: q 0..4095, k 4096..5119, v 5120..6143
__device__ float g_rq  [S_ * H_ * DH_];       // rope'd q [s][32][128]
__device__ float g_rk  [S_ * KVH_ * DH_];     // rope'd k [s][8][128]
__device__ float g_ckin[KVH_ * NC_ * CDIM_];  // [512][2048]
__device__ float g_cvin[KVH_ * NC_ * CDIM_];
__device__ float g_h1  [KVH_ * NC_ * CDIM_];  // MLP hidden (reused for K then V)
__device__ float g_ckb [KVH_ * NC_ * DH_];    // [512][128]
__device__ float g_cvb [KVH_ * NC_ * DH_];
__device__ float g_ck  [KVH_ * (NC_ + 1) * DH_]; // [8][65][128] (mem at j=0)
__device__ float g_cv  [KVH_ * (NC_ + 1) * DH_];
__device__ float g_cout[S_ * H_ * DH_];
__device__ float g_fout[S_ * H_ * DH_];
__device__ float g_sout[S_ * H_ * DH_];
__device__ int   g_sel [KVH_ * S_ * 5];
__device__ int   g_selok[KVH_ * S_ * 4];
__device__ float g_gates[S_ * 96];
__device__ float g_mid [S_ * D_];

// ---------------- generic SGEMM: C[M,N] = A[M,K] @ B[N,K]^T (+bias)(act) --------
// ACT: 0 none, 1 relu, 2 sigmoid
#define BM 128
#define BN 128
#define BK 16

template <int ACT>
__global__ void __launch_bounds__(256)
gemm_bt(const float* __restrict__ A, const float* __restrict__ B,
        const float* __restrict__ bias, float* __restrict__ C,
        int M, int N, int K) {
    __shared__ float As[BK][BM + 4];
    __shared__ float Bs[BK][BN + 4];
    const int tid = threadIdx.x;
    const int tx = tid & 15, ty = tid >> 4;
    const int bm = blockIdx.y * BM, bn = blockIdx.x * BN;
    const int lr = tid >> 1;            // 0..127
    const int lc = (tid & 1) * 8;       // 0 or 8

    float acc[8][8];
#pragma unroll
    for (int i = 0; i < 8; i++)
#pragma unroll
        for (int j = 0; j < 8; j++) acc[i][j] = 0.f;

    for (int k0 = 0; k0 < K; k0 += BK) {
        const int ar = bm + lr;
        const int br = bn + lr;
#pragma unroll
        for (int u = 0; u < 8; u++) {
            int kk = lc + u;
            float va = 0.f, vb = 0.f;
            if (ar < M) va = A[(size_t)ar * K + k0 + kk];
            if (br < N) vb = B[(size_t)br * K + k0 + kk];
            As[kk][lr] = va;
            Bs[kk][lr] = vb;
        }
        __syncthreads();
#pragma unroll
        for (int kk = 0; kk < BK; kk++) {
            float ra[8], rb[8];
#pragma unroll
            for (int i = 0; i < 8; i++) ra[i] = As[kk][ty * 8 + i];
#pragma unroll
            for (int j = 0; j < 8; j++) rb[j] = Bs[kk][tx * 8 + j];
#pragma unroll
            for (int i = 0; i < 8; i++)
#pragma unroll
                for (int j = 0; j < 8; j++) acc[i][j] += ra[i] * rb[j];
        }
        __syncthreads();
    }

#pragma unroll
    for (int i = 0; i < 8; i++) {
        int row = bm + ty * 8 + i;
        if (row >= M) continue;
#pragma unroll
        for (int j = 0; j < 8; j++) {
            int col = bn + tx * 8 + j;
            if (col >= N) continue;
            float v = acc[i][j];
            if (bias) v += bias[col];
            if (ACT == 1) v = fmaxf(v, 0.f);
            if (ACT == 2) v = 1.f / (1.f + expf(-v));
            C[(size_t)row * N + col] = v;
        }
    }
}

// ---------------- build compressed MLP inputs --------------------------------
__global__ void build_cin_kernel(const float* __restrict__ k_pos,
                                 const float* __restrict__ v_pos) {
    int idx = blockIdx.x * blockDim.x + threadIdx.x;   // 512*2048
    if (idx >= KVH_ * NC_ * CDIM_) return;
    int r = idx >> 11, col = idx & 2047;
    int h = r >> 6, c = r & 63;
    int t = col >> 7, d = col & 127;
    int s = c * CB_ + t;
    size_t base = (size_t)s * NQKV_ + h * DH_ + d;
    int pidx = (h * CB_ + t) * DH_ + d;
    g_ckin[idx] = g_qkv[base + 4096] + k_pos[pidx];
    g_cvin[idx] = g_qkv[base + 5120] + v_pos[pidx];
}

// ---------------- scatter compressed K/V (prepend mem token) -----------------
__global__ void scatter_c_kernel(const float* __restrict__ mem_kv) {
    int idx = blockIdx.x * blockDim.x + threadIdx.x;   // 8*65*128
    if (idx >= KVH_ * (NC_ + 1) * DH_) return;
    int d = idx & 127, jh = idx >> 7;
    int h = jh / (NC_ + 1), j = jh % (NC_ + 1);
    float kv, vv;
    if (j == 0) {
        kv = mem_kv[h * DH_ + d];
        vv = mem_kv[KVH_ * DH_ + h * DH_ + d];
    } else {
        int r = (h * NC_ + (j - 1)) * DH_ + d;
        kv = g_ckb[r];
        vv = g_cvb[r];
    }
    g_ck[idx] = kv;
    g_cv[idx] = vv;
}

// ---------------- RoPE (interleaved, theta=10000) ----------------------------
__global__ void rope_kernel() {
    int i = blockIdx.x;        // seq
    int y = blockIdx.y;        // 0..31 q heads, 32..39 k heads
    int p = threadIdx.x;       // pair 0..63
    const float* src;
    float* dst;
    if (y < H_) {
        src = g_qkv + (size_t)i * NQKV_ + y * DH_;
        dst = g_rq + ((size_t)i * H_ + y) * DH_;
    } else {
        src = g_qkv + (size_t)i * NQKV_ + 4096 + (y - H_) * DH_;
        dst = g_rk + ((size_t)i * KVH_ + (y - H_)) * DH_;
    }
    float inv = (float)pow(10000.0, -(double)(2 * p) / 128.0);
    float ang = (float)i * inv;
    float sn, cs;
    sincosf(ang, &sn, &cs);
    float x0 = src[2 * p], x1 = src[2 * p + 1];
    dst[2 * p]     = x0 * cs - x1 * sn;
    dst[2 * p + 1] = x1 * cs + x0 * sn;
}

// ---------------- compressed attention + importance top-k --------------------
__global__ void comp_attn_kernel() {
    int i = blockIdx.x;   // query
    int h = blockIdx.y;   // kvh
    int tid = threadIdx.x;          // 128
    int g = tid >> 5, lane = tid & 31;
    __shared__ float sim[4][65];
    __shared__ float imp[64];

    const float* qp = g_qkv + (size_t)i * NQKV_ + (h * 4 + g) * DH_;
    float q0 = qp[lane], q1 = qp[lane + 32], q2 = qp[lane + 64], q3 = qp[lane + 96];

    for (int j = 0; j < 65; j++) {
        const float* kp = g_ck + (h * 65 + j) * DH_;
        float d = q0 * kp[lane] + q1 * kp[lane + 32] + q2 * kp[lane + 64] + q3 * kp[lane + 96];
#pragma unroll
        for (int o = 16; o > 0; o >>= 1) d += __shfl_down_sync(0xffffffffu, d, o);
        if (lane == 0) {
            bool vis = (j == 0) || (i >= j * CB_);
            sim[g][j] = vis ? d * SCALE_ : NEGF;
        }
    }
    __syncwarp();

    // per-head softmax + weighted sum over cv
    float m = NEGF;
    for (int j = lane; j < 65; j += 32) m = fmaxf(m, sim[g][j]);
#pragma unroll
    for (int o = 16; o > 0; o >>= 1) m = fmaxf(m, __shfl_xor_sync(0xffffffffu, m, o));
    float den = 0.f;
    for (int j = lane; j < 65; j += 32) den += expf(sim[g][j] - m);
#pragma unroll
    for (int o = 16; o > 0; o >>= 1) den += __shfl_xor_sync(0xffffffffu, den, o);
    float invden = 1.f / den;

    float o0 = 0, o1 = 0, o2 = 0, o3 = 0;
    for (int j = 0; j < 65; j++) {
        float p = expf(sim[g][j] - m) * invden;
        const float* vp = g_cv + (h * 65 + j) * DH_;
        o0 += p * vp[lane];
        o1 += p * vp[lane + 32];
        o2 += p * vp[lane + 64];
        o3 += p * vp[lane + 96];
    }
    float* op = g_cout + ((size_t)i * H_ + h * 4 + g) * DH_;
    op[lane] = o0; op[lane + 32] = o1; op[lane + 64] = o2; op[lane + 96] = o3;

    __syncthreads();

    // importance: mean over 4 grouped heads of MASKED logits (mem excluded)
    if (tid < 64) {
        float s = sim[0][tid + 1] + sim[1][tid + 1] + sim[2][tid + 1] + sim[3][tid + 1];
        imp[tid] = 0.25f * s;   // 4*(-FLT_MAX) -> -inf, matching jnp overflow
    }
    __syncthreads();

    if (tid == 0) {
        float mm = -1000.f;   // sentinel
        for (int j = 0; j < 64; j++) mm = fmaxf(mm, imp[j]);
        float dd = expf(-1000.f - mm);
        for (int j = 0; j < 64; j++) dd += expf(imp[j] - mm);
        float inv = 1.f / dd;
        unsigned long long used = 0ull;
        int* sp = g_sel + (h * S_ + i) * 5;
        int* okp = g_selok + (h * S_ + i) * 4;
        for (int r = 0; r < NSEL_; r++) {
            float bp = -1.f;
            int bj = 0;
            for (int j = 0; j < 64; j++) {
                if ((used >> j) & 1ull) continue;
                float p = expf(imp[j] - mm) * inv;
                if (p > bp) { bp = p; bj = j; }   // strict > : lowest-index tiebreak
            }
            used |= 1ull << bj;
            sp[r] = bj;
            okp[r] = (bp > 1e-10f) ? 1 : 0;
        }
        sp[4] = i >> 4;   // own block
    }
}

// ---------------- fine (selected-block) attention ----------------------------
__global__ void fine_attn_kernel() {
    int i = blockIdx.x, qh = blockIdx.y;
    int h = qh >> 2;
    int tid = threadIdx.x;   // 128
    int w = tid >> 5, lane = tid & 31;
    __shared__ float sim[80];
    __shared__ int sblk[5];
    __shared__ int sok[4];
    __shared__ float ssoft[2];

    if (tid < 5) sblk[tid] = g_sel[(h * S_ + i) * 5 + tid];
    if (tid < 4) sok[tid] = g_selok[(h * S_ + i) * 4 + tid];
    __syncthreads();

    const float* qp = g_rq + ((size_t)i * H_ + qh) * DH_;
    float q0 = qp[lane], q1 = qp[lane + 32], q2 = qp[lane + 64], q3 = qp[lane + 96];

    for (int j = w * 20; j < w * 20 + 20; j++) {
        int r = j >> 4, t = j & 15;
        int skey = sblk[r] * SB_ + t;
        const float* kp = g_rk + ((size_t)skey * KVH_ + h) * DH_;
        float d = q0 * kp[lane] + q1 * kp[lane + 32] + q2 * kp[lane + 64] + q3 * kp[lane + 96];
#pragma unroll
        for (int o = 16; o > 0; o >>= 1) d += __shfl_down_sync(0xffffffffu, d, o);
        if (lane == 0) {
            bool vis = (r < 4) ? (sok[r] != 0) : (t <= (i & 15));
            sim[j] = vis ? d * SCALE_ : NEGF;
        }
    }
    __syncthreads();

    if (tid == 0) {
        float m = NEGF;
        for (int j = 0; j < 80; j++) m = fmaxf(m, sim[j]);
        float dd = 0.f;
        for (int j = 0; j < 80; j++) dd += expf(sim[j] - m);
        ssoft[0] = m;
        ssoft[1] = 1.f / dd;
    }
    __syncthreads();
    if (tid < 80) sim[tid] = expf(sim[tid] - ssoft[0]) * ssoft[1];
    __syncthreads();

    float acc = 0.f;
    int d = tid;
    for (int j = 0; j < 80; j++) {
        int r = j >> 4, t = j & 15;
        int skey = sblk[r] * SB_ + t;
        acc += sim[j] * g_qkv[(size_t)skey * NQKV_ + 5120 + h * DH_ + d];
    }
    g_fout[((size_t)i * H_ + qh) * DH_ + d] = acc;
}

// ---------------- sliding-window attention (65 keys, clipped) ----------------
__global__ void slide_attn_kernel() {
    int i = blockIdx.x, qh = blockIdx.y;
    int h = qh >> 2;
    int tid = threadIdx.x;   // 128
    int w = tid >> 5, lane = tid & 31;
    __shared__ float sim[65];
    __shared__ float ssoft[2];

    int j0 = i - WIN_;
    if (j0 < 0) j0 = 0;
    int nj = i - j0 + 1;

    const float* qp = g_rq + ((size_t)i * H_ + qh) * DH_;
    float q0 = qp[lane], q1 = qp[lane + 32], q2 = qp[lane + 64], q3 = qp[lane + 96];

    for (int j = w; j < nj; j += 4) {
        int s = j0 + j;
        const float* kp = g_rk + ((size_t)s * KVH_ + h) * DH_;
        float d = q0 * kp[lane] + q1 * kp[lane + 32] + q2 * kp[lane + 64] + q3 * kp[lane + 96];
#pragma unroll
        for (int o = 16; o > 0; o >>= 1) d += __shfl_down_sync(0xffffffffu, d, o);
        if (lane == 0) sim[j] = d * SCALE_;
    }
    __syncthreads();

    if (tid == 0) {
        float m = NEGF;
        for (int j = 0; j < nj; j++) m = fmaxf(m, sim[j]);
        float dd = 0.f;
        for (int j = 0; j < nj; j++) dd += expf(sim[j] - m);
        ssoft[0] = m;
        ssoft[1] = 1.f / dd;
    }
    __syncthreads();
    if (tid < nj) sim[tid] = expf(sim[tid] - ssoft[0]) * ssoft[1];
    __syncthreads();

    float acc = 0.f;
    int d = tid;
    for (int j = 0; j < nj; j++)
        acc += sim[j] * g_qkv[(size_t)(j0 + j) * NQKV_ + 5120 + h * DH_ + d];
    g_sout[((size_t)i * H_ + qh) * DH_ + d] = acc;
}

// ---------------- gate-combine ------------------------------------------------
__global__ void combine_kernel() {
    int idx = blockIdx.x * blockDim.x + threadIdx.x;   // 1024*4096
    if (idx >= S_ * D_) return;
    int i = idx >> 12, hd = idx & 4095, hh = hd >> 7;
    const float* gp = g_gates + i * 96 + hh * 3;
    g_mid[idx] = gp[0] * g_cout[idx] + gp[1] * g_fout[idx] + gp[2] * g_sout[idx];
}

// ---------------- launch ------------------------------------------------------
extern "C" void kernel_launch(void* const* d_in, const int* in_sizes, int n_in,
                              void* d_out, int out_size) {
    const float* hidden = (const float*)d_in[0];
    const float* w_qkv  = (const float*)d_in[1];
    const float* w_o    = (const float*)d_in[2];
    const float* k_pos  = (const float*)d_in[3];
    const float* v_pos  = (const float*)d_in[4];
    const float* k_w1   = (const float*)d_in[5];
    const float* k_b1   = (const float*)d_in[6];
    const float* k_w2   = (const float*)d_in[7];
    const float* k_b2   = (const float*)d_in[8];
    const float* v_w1   = (const float*)d_in[9];
    const float* v_b1   = (const float*)d_in[10];
    const float* v_w2   = (const float*)d_in[11];
    const float* v_b2   = (const float*)d_in[12];
    const float* mem_kv = (const float*)d_in[13];
    const float* w_gate = (const float*)d_in[14];
    const float* b_gate = (const float*)d_in[15];
    float* out = (float*)d_out;

    float *qkv, *ckin, *cvin, *h1, *ckb, *cvb, *gates, *mid;
    cudaGetSymbolAddress((void**)&qkv,   g_qkv);
    cudaGetSymbolAddress((void**)&ckin,  g_ckin);
    cudaGetSymbolAddress((void**)&cvin,  g_cvin);
    cudaGetSymbolAddress((void**)&h1,    g_h1);
    cudaGetSymbolAddress((void**)&ckb,   g_ckb);
    cudaGetSymbolAddress((void**)&cvb,   g_cvb);
    cudaGetSymbolAddress((void**)&gates, g_gates);
    cudaGetSymbolAddress((void**)&mid,   g_mid);

    // 1. QKV projection
    gemm_bt<0><<<dim3(NQKV_ / BN, S_ / BM), 256>>>(hidden, w_qkv, nullptr, qkv,
                                                   S_, NQKV_, D_);
    // 2. compressed MLP inputs
    build_cin_kernel<<<(KVH_ * NC_ * CDIM_ + 255) / 256, 256>>>(k_pos, v_pos);
    // 3. K compress MLP
    gemm_bt<1><<<dim3(CDIM_ / BN, (KVH_ * NC_ + BM - 1) / BM), 256>>>(
        ckin, k_w1, k_b1, h1, KVH_ * NC_, CDIM_, CDIM_);
    gemm_bt<0><<<dim3(1, (KVH_ * NC_ + BM - 1) / BM), 256>>>(
        h1, k_w2, k_b2, ckb, KVH_ * NC_, DH_, CDIM_);
    // 4. V compress MLP (reuses h1)
    gemm_bt<1><<<dim3(CDIM_ / BN, (KVH_ * NC_ + BM - 1) / BM), 256>>>(
        cvin, v_w1, v_b1, h1, KVH_ * NC_, CDIM_, CDIM_);
    gemm_bt<0><<<dim3(1, (KVH_ * NC_ + BM - 1) / BM), 256>>>(
        h1, v_w2, v_b2, cvb, KVH_ * NC_, DH_, CDIM_);
    // 5. prepend mem token
    scatter_c_kernel<<<(KVH_ * (NC_ + 1) * DH_ + 255) / 256, 256>>>(mem_kv);
    // 6. RoPE
    rope_kernel<<<dim3(S_, H_ + KVH_), 64>>>();
    // 7. compressed attention + selection
    comp_attn_kernel<<<dim3(S_, KVH_), 128>>>();
    // 8. fine attention
    fine_attn_kernel<<<dim3(S_, H_), 128>>>();
    // 9. sliding window attention
    slide_attn_kernel<<<dim3(S_, H_), 128>>>();
    // 10. gates
    gemm_bt<2><<<dim3(1, S_ / BM), 256>>>(hidden, w_gate, b_gate, gates,
                                          S_, 96, D_);
    // 11. combine
    combine_kernel<<<(S_ * D_ + 255) / 256, 256>>>();
    // 12. output projection
    gemm_bt<0><<<dim3(D_ / BN, S_ / BM), 256>>>(mid, w_o, nullptr, out,
                                                S_, D_, D_);
}

// round 5
// speedup vs baseline: 2.1418x; 2.1418x over previous
#include <cuda_runtime.h>
#include <cuda_bf16.h>
#include <math.h>

// ---------------- problem constants ----------------
#define S_   1024
#define H_   32
#define KVH_ 8
#define DH_  128
#define D_   4096
#define CB_  16
#define NC_  64        // S/CB
#define SB_  16
#define NSEL_ 4
#define WIN_ 64
#define NQKV_ 6144     // H*DH + 2*KVH*DH
#define CDIM_ 2048     // CB*DH
#define NEGF (-3.402823466e38f)
#define SCALE_ 0.08838834764831844056f  // 128^-0.5

// ---------------- scratch (no allocs allowed) ----------------
__device__ float g_qkv [S_ * NQKV_];
__device__ float g_rq  [S_ * H_ * DH_];
__device__ float g_rk  [S_ * KVH_ * DH_];
__device__ float g_ckin[KVH_ * NC_ * CDIM_];
__device__ float g_cvin[KVH_ * NC_ * CDIM_];
__device__ float g_h1  [KVH_ * NC_ * CDIM_];
__device__ float g_ckb [KVH_ * NC_ * DH_];
__device__ float g_cvb [KVH_ * NC_ * DH_];
__device__ float g_ck  [KVH_ * (NC_ + 1) * DH_];
__device__ float g_cv  [KVH_ * (NC_ + 1) * DH_];
__device__ float g_cout[S_ * H_ * DH_];
__device__ float g_fout[S_ * H_ * DH_];
__device__ float g_sout[S_ * H_ * DH_];
__device__ int   g_sel [KVH_ * S_ * 5];
__device__ int   g_selok[KVH_ * S_ * 4];
__device__ float g_gates[S_ * 96];
__device__ float g_mid [S_ * D_];
__device__ float g_part[16 * 1024 * 96];   // split-K partials (max: gates)

// =================== TF32 tensor-core GEMM ===================
// C[M,N] = A[M,K] @ B[N,K]^T  using 3xTF32 (fp32-accurate)
// Tile 128x128x32, 256 threads, warp tile 64x32 (2x4 warp grid).
// Split-K via blockIdx.z: if gridDim.z>1 write raw partials to `part`.
#define TBM 128
#define TBN 128
#define TBK 32
#define TSTRIDE 36           // 32 + 4 pad (floats)
#define TSMEM_STAGE (TBM * TSTRIDE)
#define TSMEM_FLOATS (4 * TSMEM_STAGE)   // A[2 stages] + B[2 stages]
#define TSMEM_BYTES (TSMEM_FLOATS * 4)

__device__ __forceinline__ unsigned f2tf(float x) {
    unsigned r;
    asm("cvt.rna.tf32.f32 %0, %1;" : "=r"(r) : "f"(x));
    return r;
}

__device__ __forceinline__ void mma_tf32(float c[4], unsigned a0, unsigned a1,
                                         unsigned a2, unsigned a3,
                                         unsigned b0, unsigned b1) {
    asm volatile(
        "mma.sync.aligned.m16n8k8.row.col.f32.tf32.tf32.f32 "
        "{%0,%1,%2,%3}, {%4,%5,%6,%7}, {%8,%9}, {%0,%1,%2,%3};\n"
        : "+f"(c[0]), "+f"(c[1]), "+f"(c[2]), "+f"(c[3])
        : "r"(a0), "r"(a1), "r"(a2), "r"(a3), "r"(b0), "r"(b1));
}

__device__ __forceinline__ void cp16(unsigned dst, const void* src, int zfill) {
    asm volatile("cp.async.ca.shared.global [%0], [%1], 16, %2;\n"
                 :: "r"(dst), "l"(src), "r"(zfill));
}

// ACT: 0 none, 1 relu. NGUARD: bounds-check N (B rows / C cols).
template <int ACT, bool NGUARD>
__global__ void __launch_bounds__(256, 1)
gemm_tf32(const float* __restrict__ A, const float* __restrict__ B,
          const float* __restrict__ bias, float* __restrict__ C,
          int M, int N, int K, int klen, float* __restrict__ part) {
    extern __shared__ float smem[];
    float* As = smem;                       // [2][128*36]
    float* Bs = smem + 2 * TSMEM_STAGE;     // [2][128*36]

    const int tid = threadIdx.x;
    const int wid = tid >> 5, lane = tid & 31;
    const int warp_m = wid >> 2;            // 0..1 -> 64-row slab
    const int warp_n = wid & 3;             // 0..3 -> 32-col slab
    const int g = lane >> 2, tg = lane & 3;
    const int bm = blockIdx.y * TBM, bn = blockIdx.x * TBN;
    const int kglob = blockIdx.z * klen;

    // loader mapping: 2 threads per 32-float row, 4x 16B chunks each
    const int lrow = tid >> 1;
    const int lcol = (tid & 1) * 16;
    int brow = bn + lrow;
    int browc = NGUARD ? (brow < N ? brow : N - 1) : brow;
    const int bzf = (!NGUARD || brow < N) ? 16 : 0;

    const unsigned s_as = (unsigned)__cvta_generic_to_shared(As);
    const unsigned s_bs = (unsigned)__cvta_generic_to_shared(Bs);

    float acc[4][4][4];
#pragma unroll
    for (int i = 0; i < 4; i++)
#pragma unroll
        for (int j = 0; j < 4; j++)
#pragma unroll
            for (int e = 0; e < 4; e++) acc[i][j][e] = 0.f;

    const int ntiles = klen / TBK;
    const float* Ab = A + (size_t)(bm + lrow) * K + kglob + lcol;
    const float* Bb = B + (size_t)browc * K + kglob + lcol;
    const unsigned asb = s_as + (unsigned)(lrow * TSTRIDE + lcol) * 4u;
    const unsigned bsb = s_bs + (unsigned)(lrow * TSTRIDE + lcol) * 4u;

#define TLOAD(stg, t)                                                        \
    do {                                                                     \
        const float* ap = Ab + (t) * TBK;                                    \
        const float* bp = Bb + (t) * TBK;                                    \
        unsigned ad = asb + (stg) * TSMEM_STAGE * 4u;                        \
        unsigned bd = bsb + (stg) * TSMEM_STAGE * 4u;                        \
        _Pragma("unroll")                                                    \
        for (int u = 0; u < 4; u++) {                                        \
            cp16(ad + u * 16u, ap + u * 4, 16);                              \
            cp16(bd + u * 16u, bp + u * 4, bzf);                             \
        }                                                                    \
        asm volatile("cp.async.commit_group;\n");                            \
    } while (0)

    TLOAD(0, 0);

    for (int t = 0; t < ntiles; t++) {
        if (t + 1 < ntiles) {
            TLOAD((t + 1) & 1, t + 1);
            asm volatile("cp.async.wait_group 1;\n");
        } else {
            asm volatile("cp.async.wait_group 0;\n");
        }
        __syncthreads();

        const float* as = As + (t & 1) * TSMEM_STAGE;
        const float* bs = Bs + (t & 1) * TSMEM_STAGE;
#pragma unroll
        for (int ks = 0; ks < 4; ks++) {
            const int cb = ks * 8;
            unsigned ah[4][4], al[4][4];
#pragma unroll
            for (int mt = 0; mt < 4; mt++) {
                const int r0 = (warp_m * 64 + mt * 16 + g) * TSTRIDE;
                const int r1 = r0 + 8 * TSTRIDE;
                float x0 = as[r0 + cb + tg];
                float x1 = as[r1 + cb + tg];
                float x2 = as[r0 + cb + tg + 4];
                float x3 = as[r1 + cb + tg + 4];
                ah[mt][0] = f2tf(x0); al[mt][0] = f2tf(x0 - __uint_as_float(ah[mt][0]));
                ah[mt][1] = f2tf(x1); al[mt][1] = f2tf(x1 - __uint_as_float(ah[mt][1]));
                ah[mt][2] = f2tf(x2); al[mt][2] = f2tf(x2 - __uint_as_float(ah[mt][2]));
                ah[mt][3] = f2tf(x3); al[mt][3] = f2tf(x3 - __uint_as_float(ah[mt][3]));
            }
            unsigned bh[4][2], bl[4][2];
#pragma unroll
            for (int nt = 0; nt < 4; nt++) {
                const int rn = (warp_n * 32 + nt * 8 + g) * TSTRIDE;
                float y0 = bs[rn + cb + tg];
                float y1 = bs[rn + cb + tg + 4];
                bh[nt][0] = f2tf(y0); bl[nt][0] = f2tf(y0 - __uint_as_float(bh[nt][0]));
                bh[nt][1] = f2tf(y1); bl[nt][1] = f2tf(y1 - __uint_as_float(bh[nt][1]));
            }
#pragma unroll
            for (int mt = 0; mt < 4; mt++)
#pragma unroll
                for (int nt = 0; nt < 4; nt++) {
                    mma_tf32(acc[mt][nt], al[mt][0], al[mt][1], al[mt][2], al[mt][3],
                             bh[nt][0], bh[nt][1]);
                    mma_tf32(acc[mt][nt], ah[mt][0], ah[mt][1], ah[mt][2], ah[mt][3],
                             bl[nt][0], bl[nt][1]);
                    mma_tf32(acc[mt][nt], ah[mt][0], ah[mt][1], ah[mt][2], ah[mt][3],
                             bh[nt][0], bh[nt][1]);
                }
        }
        __syncthreads();
    }
#undef TLOAD

    const bool split = (gridDim.z > 1);
#pragma unroll
    for (int mt = 0; mt < 4; mt++) {
#pragma unroll
        for (int nt = 0; nt < 4; nt++) {
#pragma unroll
            for (int e = 0; e < 4; e++) {
                int row = bm + warp_m * 64 + mt * 16 + g + ((e >= 2) ? 8 : 0);
                int col = bn + warp_n * 32 + nt * 8 + 2 * tg + (e & 1);
                if (NGUARD && col >= N) continue;
                float v = acc[mt][nt][e];
                if (split) {
                    g_part[(size_t)blockIdx.z * M * N + (size_t)row * N + col] = v;
                } else {
                    if (bias) v += bias[col];
                    if (ACT == 1) v = fmaxf(v, 0.f);
                    C[(size_t)row * N + col] = v;
                }
            }
        }
    }
}

// split-K reduce: C = act(sum_z part + bias). ACT: 0 none, 2 sigmoid
template <int ACT>
__global__ void reduce_splitk(const float* __restrict__ bias,
                              float* __restrict__ C, int MN, int N, int splits) {
    int idx = blockIdx.x * blockDim.x + threadIdx.x;
    if (idx >= MN) return;
    float s = 0.f;
    for (int z = 0; z < splits; z++) s += g_part[(size_t)z * MN + idx];
    if (bias) s += bias[idx % N];
    if (ACT == 2) s = 1.f / (1.f + expf(-s));
    C[idx] = s;
}

// ---------------- build compressed MLP inputs --------------------------------
__global__ void build_cin_kernel(const float* __restrict__ k_pos,
                                 const float* __restrict__ v_pos) {
    int idx = blockIdx.x * blockDim.x + threadIdx.x;
    if (idx >= KVH_ * NC_ * CDIM_) return;
    int r = idx >> 11, col = idx & 2047;
    int h = r >> 6, c = r & 63;
    int t = col >> 7, d = col & 127;
    int s = c * CB_ + t;
    size_t base = (size_t)s * NQKV_ + h * DH_ + d;
    int pidx = (h * CB_ + t) * DH_ + d;
    g_ckin[idx] = g_qkv[base + 4096] + k_pos[pidx];
    g_cvin[idx] = g_qkv[base + 5120] + v_pos[pidx];
}

// ---------------- scatter compressed K/V (prepend mem token) -----------------
__global__ void scatter_c_kernel(const float* __restrict__ mem_kv) {
    int idx = blockIdx.x * blockDim.x + threadIdx.x;
    if (idx >= KVH_ * (NC_ + 1) * DH_) return;
    int d = idx & 127, jh = idx >> 7;
    int h = jh / (NC_ + 1), j = jh % (NC_ + 1);
    float kv, vv;
    if (j == 0) {
        kv = mem_kv[h * DH_ + d];
        vv = mem_kv[KVH_ * DH_ + h * DH_ + d];
    } else {
        int r = (h * NC_ + (j - 1)) * DH_ + d;
        kv = g_ckb[r];
        vv = g_cvb[r];
    }
    g_ck[idx] = kv;
    g_cv[idx] = vv;
}

// ---------------- RoPE (interleaved, theta=10000) ----------------------------
__global__ void rope_kernel() {
    int i = blockIdx.x;
    int y = blockIdx.y;
    int p = threadIdx.x;
    const float* src;
    float* dst;
    if (y < H_) {
        src = g_qkv + (size_t)i * NQKV_ + y * DH_;
        dst = g_rq + ((size_t)i * H_ + y) * DH_;
    } else {
        src = g_qkv + (size_t)i * NQKV_ + 4096 + (y - H_) * DH_;
        dst = g_rk + ((size_t)i * KVH_ + (y - H_)) * DH_;
    }
    float inv = (float)pow(10000.0, -(double)(2 * p) / 128.0);
    float ang = (float)i * inv;
    float sn, cs;
    sincosf(ang, &sn, &cs);
    float x0 = src[2 * p], x1 = src[2 * p + 1];
    dst[2 * p]     = x0 * cs - x1 * sn;
    dst[2 * p + 1] = x1 * cs + x0 * sn;
}

// ---------------- compressed attention + importance top-k --------------------
__global__ void comp_attn_kernel() {
    int i = blockIdx.x;
    int h = blockIdx.y;
    int tid = threadIdx.x;
    int g = tid >> 5, lane = tid & 31;
    __shared__ float sim[4][65];
    __shared__ float imp[64];

    const float* qp = g_qkv + (size_t)i * NQKV_ + (h * 4 + g) * DH_;
    float q0 = qp[lane], q1 = qp[lane + 32], q2 = qp[lane + 64], q3 = qp[lane + 96];

    for (int j = 0; j < 65; j++) {
        const float* kp = g_ck + (h * 65 + j) * DH_;
        float d = q0 * kp[lane] + q1 * kp[lane + 32] + q2 * kp[lane + 64] + q3 * kp[lane + 96];
#pragma unroll
        for (int o = 16; o > 0; o >>= 1) d += __shfl_down_sync(0xffffffffu, d, o);
        if (lane == 0) {
            bool vis = (j == 0) || (i >= j * CB_);
            sim[g][j] = vis ? d * SCALE_ : NEGF;
        }
    }
    __syncwarp();

    float m = NEGF;
    for (int j = lane; j < 65; j += 32) m = fmaxf(m, sim[g][j]);
#pragma unroll
    for (int o = 16; o > 0; o >>= 1) m = fmaxf(m, __shfl_xor_sync(0xffffffffu, m, o));
    float den = 0.f;
    for (int j = lane; j < 65; j += 32) den += expf(sim[g][j] - m);
#pragma unroll
    for (int o = 16; o > 0; o >>= 1) den += __shfl_xor_sync(0xffffffffu, den, o);
    float invden = 1.f / den;

    float o0 = 0, o1 = 0, o2 = 0, o3 = 0;
    for (int j = 0; j < 65; j++) {
        float p = expf(sim[g][j] - m) * invden;
        const float* vp = g_cv + (h * 65 + j) * DH_;
        o0 += p * vp[lane];
        o1 += p * vp[lane + 32];
        o2 += p * vp[lane + 64];
        o3 += p * vp[lane + 96];
    }
    float* op = g_cout + ((size_t)i * H_ + h * 4 + g) * DH_;
    op[lane] = o0; op[lane + 32] = o1; op[lane + 64] = o2; op[lane + 96] = o3;

    __syncthreads();

    if (tid < 64) {
        float s = sim[0][tid + 1] + sim[1][tid + 1] + sim[2][tid + 1] + sim[3][tid + 1];
        imp[tid] = 0.25f * s;
    }
    __syncthreads();

    if (tid == 0) {
        float mm = -1000.f;
        for (int j = 0; j < 64; j++) mm = fmaxf(mm, imp[j]);
        float dd = expf(-1000.f - mm);
        for (int j = 0; j < 64; j++) dd += expf(imp[j] - mm);
        float inv = 1.f / dd;
        unsigned long long used = 0ull;
        int* sp = g_sel + (h * S_ + i) * 5;
        int* okp = g_selok + (h * S_ + i) * 4;
        for (int r = 0; r < NSEL_; r++) {
            float bp = -1.f;
            int bj = 0;
            for (int j = 0; j < 64; j++) {
                if ((used >> j) & 1ull) continue;
                float p = expf(imp[j] - mm) * inv;
                if (p > bp) { bp = p; bj = j; }
            }
            used |= 1ull << bj;
            sp[r] = bj;
            okp[r] = (bp > 1e-10f) ? 1 : 0;
        }
        sp[4] = i >> 4;
    }
}

// ---------------- fine (selected-block) attention ----------------------------
__global__ void fine_attn_kernel() {
    int i = blockIdx.x, qh = blockIdx.y;
    int h = qh >> 2;
    int tid = threadIdx.x;
    int w = tid >> 5, lane = tid & 31;
    __shared__ float sim[80];
    __shared__ int sblk[5];
    __shared__ int sok[4];
    __shared__ float ssoft[2];

    if (tid < 5) sblk[tid] = g_sel[(h * S_ + i) * 5 + tid];
    if (tid < 4) sok[tid] = g_selok[(h * S_ + i) * 4 + tid];
    __syncthreads();

    const float* qp = g_rq + ((size_t)i * H_ + qh) * DH_;
    float q0 = qp[lane], q1 = qp[lane + 32], q2 = qp[lane + 64], q3 = qp[lane + 96];

    for (int j = w * 20; j < w * 20 + 20; j++) {
        int r = j >> 4, t = j & 15;
        int skey = sblk[r] * SB_ + t;
        const float* kp = g_rk + ((size_t)skey * KVH_ + h) * DH_;
        float d = q0 * kp[lane] + q1 * kp[lane + 32] + q2 * kp[lane + 64] + q3 * kp[lane + 96];
#pragma unroll
        for (int o = 16; o > 0; o >>= 1) d += __shfl_down_sync(0xffffffffu, d, o);
        if (lane == 0) {
            bool vis = (r < 4) ? (sok[r] != 0) : (t <= (i & 15));
            sim[j] = vis ? d * SCALE_ : NEGF;
        }
    }
    __syncthreads();

    if (tid == 0) {
        float m = NEGF;
        for (int j = 0; j < 80; j++) m = fmaxf(m, sim[j]);
        float dd = 0.f;
        for (int j = 0; j < 80; j++) dd += expf(sim[j] - m);
        ssoft[0] = m;
        ssoft[1] = 1.f / dd;
    }
    __syncthreads();
    if (tid < 80) sim[tid] = expf(sim[tid] - ssoft[0]) * ssoft[1];
    __syncthreads();

    float acc = 0.f;
    int d = tid;
    for (int j = 0; j < 80; j++) {
        int r = j >> 4, t = j & 15;
        int skey = sblk[r] * SB_ + t;
        acc += sim[j] * g_qkv[(size_t)skey * NQKV_ + 5120 + h * DH_ + d];
    }
    g_fout[((size_t)i * H_ + qh) * DH_ + d] = acc;
}

// ---------------- sliding-window attention (65 keys, clipped) ----------------
__global__ void slide_attn_kernel() {
    int i = blockIdx.x, qh = blockIdx.y;
    int h = qh >> 2;
    int tid = threadIdx.x;
    int w = tid >> 5, lane = tid & 31;
    __shared__ float sim[65];
    __shared__ float ssoft[2];

    int j0 = i - WIN_;
    if (j0 < 0) j0 = 0;
    int nj = i - j0 + 1;

    const float* qp = g_rq + ((size_t)i * H_ + qh) * DH_;
    float q0 = qp[lane], q1 = qp[lane + 32], q2 = qp[lane + 64], q3 = qp[lane + 96];

    for (int j = w; j < nj; j += 4) {
        int s = j0 + j;
        const float* kp = g_rk + ((size_t)s * KVH_ + h) * DH_;
        float d = q0 * kp[lane] + q1 * kp[lane + 32] + q2 * kp[lane + 64] + q3 * kp[lane + 96];
#pragma unroll
        for (int o = 16; o > 0; o >>= 1) d += __shfl_down_sync(0xffffffffu, d, o);
        if (lane == 0) sim[j] = d * SCALE_;
    }
    __syncthreads();

    if (tid == 0) {
        float m = NEGF;
        for (int j = 0; j < nj; j++) m = fmaxf(m, sim[j]);
        float dd = 0.f;
        for (int j = 0; j < nj; j++) dd += expf(sim[j] - m);
        ssoft[0] = m;
        ssoft[1] = 1.f / dd;
    }
    __syncthreads();
    if (tid < nj) sim[tid] = expf(sim[tid] - ssoft[0]) * ssoft[1];
    __syncthreads();

    float acc = 0.f;
    int d = tid;
    for (int j = 0; j < nj; j++)
        acc += sim[j] * g_qkv[(size_t)(j0 + j) * NQKV_ + 5120 + h * DH_ + d];
    g_sout[((size_t)i * H_ + qh) * DH_ + d] = acc;
}

// ---------------- gate-combine ------------------------------------------------
__global__ void combine_kernel() {
    int idx = blockIdx.x * blockDim.x + threadIdx.x;
    if (idx >= S_ * D_) return;
    int i = idx >> 12, hd = idx & 4095, hh = hd >> 7;
    const float* gp = g_gates + i * 96 + hh * 3;
    g_mid[idx] = gp[0] * g_cout[idx] + gp[1] * g_fout[idx] + gp[2] * g_sout[idx];
}

// ---------------- launch ------------------------------------------------------
extern "C" void kernel_launch(void* const* d_in, const int* in_sizes, int n_in,
                              void* d_out, int out_size) {
    const float* hidden = (const float*)d_in[0];
    const float* w_qkv  = (const float*)d_in[1];
    const float* w_o    = (const float*)d_in[2];
    const float* k_pos  = (const float*)d_in[3];
    const float* v_pos  = (const float*)d_in[4];
    const float* k_w1   = (const float*)d_in[5];
    const float* k_b1   = (const float*)d_in[6];
    const float* k_w2   = (const float*)d_in[7];
    const float* k_b2   = (const float*)d_in[8];
    const float* v_w1   = (const float*)d_in[9];
    const float* v_b1   = (const float*)d_in[10];
    const float* v_w2   = (const float*)d_in[11];
    const float* v_b2   = (const float*)d_in[12];
    const float* mem_kv = (const float*)d_in[13];
    const float* w_gate = (const float*)d_in[14];
    const float* b_gate = (const float*)d_in[15];
    float* out = (float*)d_out;

    float *qkv, *ckin, *cvin, *h1, *ckb, *cvb, *gates, *mid;
    cudaGetSymbolAddress((void**)&qkv,   g_qkv);
    cudaGetSymbolAddress((void**)&ckin,  g_ckin);
    cudaGetSymbolAddress((void**)&cvin,  g_cvin);
    cudaGetSymbolAddress((void**)&h1,    g_h1);
    cudaGetSymbolAddress((void**)&ckb,   g_ckb);
    cudaGetSymbolAddress((void**)&cvb,   g_cvb);
    cudaGetSymbolAddress((void**)&gates, g_gates);
    cudaGetSymbolAddress((void**)&mid,   g_mid);

    cudaFuncSetAttribute(gemm_tf32<0, false>,
                         cudaFuncAttributeMaxDynamicSharedMemorySize, TSMEM_BYTES);
    cudaFuncSetAttribute(gemm_tf32<1, false>,
                         cudaFuncAttributeMaxDynamicSharedMemorySize, TSMEM_BYTES);
    cudaFuncSetAttribute(gemm_tf32<0, true>,
                         cudaFuncAttributeMaxDynamicSharedMemorySize, TSMEM_BYTES);

    // 1. QKV projection (1024 x 6144 x 4096)
    gemm_tf32<0, false><<<dim3(NQKV_ / TBN, S_ / TBM, 1), 256, TSMEM_BYTES>>>(
        hidden, w_qkv, nullptr, qkv, S_, NQKV_, D_, D_, nullptr);
    // 2. compressed MLP inputs
    build_cin_kernel<<<(KVH_ * NC_ * CDIM_ + 255) / 256, 256>>>(k_pos, v_pos);
    // 3. K compress MLP: W1 (512 x 2048 x 2048), W2 split-K (512 x 128 x 2048)
    gemm_tf32<1, false><<<dim3(CDIM_ / TBN, 4, 1), 256, TSMEM_BYTES>>>(
        ckin, k_w1, k_b1, h1, 512, CDIM_, CDIM_, CDIM_, nullptr);
    gemm_tf32<0, false><<<dim3(1, 4, 8), 256, TSMEM_BYTES>>>(
        h1, k_w2, nullptr, ckb, 512, DH_, CDIM_, CDIM_ / 8, nullptr);
    reduce_splitk<0><<<(512 * DH_ + 255) / 256, 256>>>(k_b2, ckb, 512 * DH_, DH_, 8);
    // 4. V compress MLP
    gemm_tf32<1, false><<<dim3(CDIM_ / TBN, 4, 1), 256, TSMEM_BYTES>>>(
        cvin, v_w1, v_b1, h1, 512, CDIM_, CDIM_, CDIM_, nullptr);
    gemm_tf32<0, false><<<dim3(1, 4, 8), 256, TSMEM_BYTES>>>(
        h1, v_w2, nullptr, cvb, 512, DH_, CDIM_, CDIM_ / 8, nullptr);
    reduce_splitk<0><<<(512 * DH_ + 255) / 256, 256>>>(v_b2, cvb, 512 * DH_, DH_, 8);
    // 5. prepend mem token
    scatter_c_kernel<<<(KVH_ * (NC_ + 1) * DH_ + 255) / 256, 256>>>(mem_kv);
    // 6. RoPE
    rope_kernel<<<dim3(S_, H_ + KVH_), 64>>>();
    // 7. compressed attention + selection
    comp_attn_kernel<<<dim3(S_, KVH_), 128>>>();
    // 8. fine attention
    fine_attn_kernel<<<dim3(S_, H_), 128>>>();
    // 9. sliding window attention
    slide_attn_kernel<<<dim3(S_, H_), 128>>>();
    // 10. gates (1024 x 96 x 4096) split-K=16 + sigmoid in reduce
    gemm_tf32<0, true><<<dim3(1, S_ / TBM, 16), 256, TSMEM_BYTES>>>(
        hidden, w_gate, nullptr, gates, S_, 96, D_, D_ / 16, nullptr);
    reduce_splitk<2><<<(S_ * 96 + 255) / 256, 256>>>(b_gate, gates, S_ * 96, 96, 16);
    // 11. combine
    combine_kernel<<<(S_ * D_ + 255) / 256, 256>>>();
    // 12. output projection (1024 x 4096 x 4096)
    gemm_tf32<0, false><<<dim3(D_ / TBN, S_ / TBM, 1), 256, TSMEM_BYTES>>>(
        mid, w_o, nullptr, out, S_, D_, D_, D_, nullptr);
}